// round 1
// baseline (speedup 1.0000x reference)
#include <cuda_runtime.h>

#define NN   4096
#define MMm  4096
#define DD   128
#define CC   4
#define NNZ  262144
#define KDIM 512
#define KADD 26214
#define NM   (NN * MMm)
#define CAPC (4u * 1024u * 1024u)

// ---------------- scratch (static device memory; no allocs allowed) ----------------
__device__ long long g_exsum[MMm * DD];      // fixed-point (2^32) segment sums
__device__ int       g_cnt[MMm];             // segment counts
__device__ float     g_nodef[NN * KDIM];     // 0.5 * normalized node features
__device__ float     g_edgef[MMm * KDIM];    // 0.5 * normalized edge features
__device__ float     g_S[NM];                // similarity matrix (masked)
__device__ unsigned  g_hist[2048];           // top-11-bit histogram
__device__ unsigned  g_cand[CAPC];           // candidate ordered-uints in threshold bucket
__device__ unsigned  g_candCount;
__device__ unsigned  g_B1;                   // selected top-11-bit bucket
__device__ unsigned  g_r1;                   // rank within bucket (1-based)
__device__ unsigned  g_Tbits;                // exact k-th largest value (ordered bits)

__device__ __forceinline__ unsigned f2ord(float f) {
    unsigned u = __float_as_uint(f);
    return (u & 0x80000000u) ? ~u : (u | 0x80000000u);
}

// ---------------- K0: zero transient state (runs every replay) ----------------
__global__ void k_zero() {
    int i  = blockIdx.x * blockDim.x + threadIdx.x;
    int st = gridDim.x * blockDim.x;
    for (int j = i; j < MMm * DD; j += st) g_exsum[j] = 0;
    for (int j = i; j < MMm;      j += st) g_cnt[j]   = 0;
    for (int j = i; j < 2048;     j += st) g_hist[j]  = 0;
    if (i == 0) g_candCount = 0;
}

// ---------------- K1: deterministic segment-sum via fixed-point atomics ----------------
__global__ void k_scatter(const float* __restrict__ X,
                          const int* __restrict__ V, const int* __restrict__ E) {
    int gid = blockIdx.x * blockDim.x + threadIdx.x;
    int i = gid >> 5;
    if (i >= NNZ) return;
    int q = gid & 31;
    int v = V[i], e = E[i];
    const float4 x = *reinterpret_cast<const float4*>(X + (size_t)v * DD + q * 4);
    unsigned long long* dst =
        reinterpret_cast<unsigned long long*>(g_exsum + (size_t)e * DD + q * 4);
    atomicAdd(dst + 0, (unsigned long long)__double2ll_rn((double)x.x * 4294967296.0));
    atomicAdd(dst + 1, (unsigned long long)__double2ll_rn((double)x.y * 4294967296.0));
    atomicAdd(dst + 2, (unsigned long long)__double2ll_rn((double)x.z * 4294967296.0));
    atomicAdd(dst + 3, (unsigned long long)__double2ll_rn((double)x.w * 4294967296.0));
    if (q == 0) atomicAdd(&g_cnt[e], 1);
}

// ---------------- K2: build 0.5 * l2norm(x * w_c) features ----------------
__global__ void k_feat(const float* __restrict__ X, const float* __restrict__ W) {
    int r   = blockIdx.x;
    int isE = blockIdx.y;
    int d   = threadIdx.x;   // 128 threads
    __shared__ float red[128];
    float x;
    if (!isE) {
        x = X[(size_t)r * DD + d];
    } else {
        long long s = g_exsum[(size_t)r * DD + d];
        float cnt   = (float)g_cnt[r];
        float sum   = (float)((double)s * (1.0 / 4294967296.0));
        x = __fdiv_rn(sum, fmaxf(cnt, 1.0f));
    }
    float* dst = isE ? g_edgef : g_nodef;
#pragma unroll
    for (int c = 0; c < CC; c++) {
        float v = x * W[c * DD + d];
        red[d] = v * v;
        __syncthreads();
        for (int s2 = 64; s2 > 0; s2 >>= 1) {
            if (d < s2) red[d] += red[d + s2];
            __syncthreads();
        }
        float nrm = __fsqrt_rn(red[0]);
        __syncthreads();
        dst[(size_t)r * KDIM + c * DD + d] = 0.5f * __fdiv_rn(v, fmaxf(nrm, 1e-12f));
    }
}

// ---------------- K3: FP32 SGEMM  S = A(4096x512) * B(4096x512)^T ----------------
__global__ void __launch_bounds__(256, 2) k_gemm() {
    const float* __restrict__ A = g_nodef;
    const float* __restrict__ B = g_edgef;
    float* __restrict__ S = g_S;

    __shared__ float As[2][8][128];
    __shared__ float Bs[2][8][128];
    const int tid = threadIdx.x;
    const int tx = tid & 15, ty = tid >> 4;
    const int bm = blockIdx.y * 128, bn = blockIdx.x * 128;
    const int lr = tid >> 1, lc = (tid & 1) * 4;
    const float* Ag = A + (size_t)(bm + lr) * KDIM + lc;
    const float* Bg = B + (size_t)(bn + lr) * KDIM + lc;

    float4 a4 = *(const float4*)Ag;
    float4 b4 = *(const float4*)Bg;

    float acc[8][8];
#pragma unroll
    for (int i = 0; i < 8; i++)
#pragma unroll
        for (int j = 0; j < 8; j++) acc[i][j] = 0.0f;

    As[0][lc + 0][lr] = a4.x; As[0][lc + 1][lr] = a4.y;
    As[0][lc + 2][lr] = a4.z; As[0][lc + 3][lr] = a4.w;
    Bs[0][lc + 0][lr] = b4.x; Bs[0][lc + 1][lr] = b4.y;
    Bs[0][lc + 2][lr] = b4.z; Bs[0][lc + 3][lr] = b4.w;
    __syncthreads();

    int buf = 0;
    const int NT = KDIM / 8;
    for (int kt = 0; kt < NT; kt++) {
        if (kt + 1 < NT) {
            a4 = *(const float4*)(Ag + (kt + 1) * 8);
            b4 = *(const float4*)(Bg + (kt + 1) * 8);
        }
#pragma unroll
        for (int kk = 0; kk < 8; kk++) {
            float ar[8], br[8];
            *(float4*)(ar)     = *(const float4*)&As[buf][kk][ty * 8];
            *(float4*)(ar + 4) = *(const float4*)&As[buf][kk][ty * 8 + 4];
            *(float4*)(br)     = *(const float4*)&Bs[buf][kk][tx * 8];
            *(float4*)(br + 4) = *(const float4*)&Bs[buf][kk][tx * 8 + 4];
#pragma unroll
            for (int i = 0; i < 8; i++)
#pragma unroll
                for (int j = 0; j < 8; j++) acc[i][j] += ar[i] * br[j];
        }
        if (kt + 1 < NT) {
            int nb = buf ^ 1;
            As[nb][lc + 0][lr] = a4.x; As[nb][lc + 1][lr] = a4.y;
            As[nb][lc + 2][lr] = a4.z; As[nb][lc + 3][lr] = a4.w;
            Bs[nb][lc + 0][lr] = b4.x; Bs[nb][lc + 1][lr] = b4.y;
            Bs[nb][lc + 2][lr] = b4.z; Bs[nb][lc + 3][lr] = b4.w;
            __syncthreads();
            buf = nb;
        }
    }
#pragma unroll
    for (int i = 0; i < 8; i++) {
        float* dst = S + (size_t)(bm + ty * 8 + i) * MMm + bn + tx * 8;
        *(float4*)(dst)     = make_float4(acc[i][0], acc[i][1], acc[i][2], acc[i][3]);
        *(float4*)(dst + 4) = make_float4(acc[i][4], acc[i][5], acc[i][6], acc[i][7]);
    }
}

// ---------------- K4: mask existing incidences ----------------
__global__ void k_mask(const int* __restrict__ V, const int* __restrict__ E) {
    int i = blockIdx.x * blockDim.x + threadIdx.x;
    if (i < NNZ) g_S[(size_t)V[i] * MMm + E[i]] = -1e30f;
}

// ---------------- K5: top-11-bit histogram ----------------
__global__ void k_hist() {
    __shared__ unsigned h[2048];
    for (int j = threadIdx.x; j < 2048; j += blockDim.x) h[j] = 0;
    __syncthreads();
    int i  = blockIdx.x * blockDim.x + threadIdx.x;
    int st = gridDim.x * blockDim.x;
    for (int j = i; j < NM; j += st) atomicAdd(&h[f2ord(g_S[j]) >> 21], 1u);
    __syncthreads();
    for (int j = threadIdx.x; j < 2048; j += blockDim.x)
        if (h[j]) atomicAdd(&g_hist[j], h[j]);
}

// ---------------- K6: find threshold bucket (1 block, 1024 thr) ----------------
__global__ void k_pick() {
    __shared__ unsigned c[2048];
    int t = threadIdx.x;
    c[t] = g_hist[t];
    c[t + 1024] = g_hist[t + 1024];
    __syncthreads();
    for (int off = 1; off < 2048; off <<= 1) {
        unsigned a0 = (t + off < 2048) ? c[t + off] : 0u;
        unsigned a1 = (t + 1024 + off < 2048) ? c[t + 1024 + off] : 0u;
        __syncthreads();
        c[t] += a0; c[t + 1024] += a1;
        __syncthreads();
    }
    for (int b = t; b < 2048; b += 1024) {
        unsigned cum = c[b], nxt = (b + 1 < 2048) ? c[b + 1] : 0u;
        if (cum >= (unsigned)KADD && nxt < (unsigned)KADD) {
            g_B1 = (unsigned)b;
            g_r1 = (unsigned)KADD - nxt;
        }
    }
}

// ---------------- K7: collect candidates in threshold bucket ----------------
__global__ void k_collect() {
    unsigned B1 = g_B1;
    int i  = blockIdx.x * blockDim.x + threadIdx.x;
    int st = gridDim.x * blockDim.x;
    for (int j = i; j < NM; j += st) {
        unsigned u = f2ord(g_S[j]);
        if ((u >> 21) == B1) {
            unsigned p = atomicAdd(&g_candCount, 1u);
            if (p < CAPC) g_cand[p] = u;
        }
    }
}

// ---------------- K8: exact k-th value via 11+10 bit refine (1 block) ----------------
__global__ void k_select() {
    __shared__ unsigned h[2048];
    __shared__ unsigned sb2, sr2;
    int t = threadIdx.x;  // 1024
    unsigned nc = g_candCount; if (nc > CAPC) nc = CAPC;
    unsigned r1 = g_r1;

    h[t] = 0; h[t + 1024] = 0;
    __syncthreads();
    for (unsigned i = t; i < nc; i += 1024)
        atomicAdd(&h[(g_cand[i] >> 10) & 2047u], 1u);
    __syncthreads();
    for (int off = 1; off < 2048; off <<= 1) {
        unsigned a0 = (t + off < 2048) ? h[t + off] : 0u;
        unsigned a1 = (t + 1024 + off < 2048) ? h[t + 1024 + off] : 0u;
        __syncthreads();
        h[t] += a0; h[t + 1024] += a1;
        __syncthreads();
    }
    for (int b = t; b < 2048; b += 1024) {
        unsigned cum = h[b], nxt = (b + 1 < 2048) ? h[b + 1] : 0u;
        if (cum >= r1 && nxt < r1) { sb2 = (unsigned)b; sr2 = r1 - nxt; }
    }
    __syncthreads();
    unsigned b2 = sb2, r2 = sr2;

    h[t] = 0;
    __syncthreads();
    for (unsigned i = t; i < nc; i += 1024) {
        unsigned u = g_cand[i];
        if (((u >> 10) & 2047u) == b2) atomicAdd(&h[u & 1023u], 1u);
    }
    __syncthreads();
    for (int off = 1; off < 1024; off <<= 1) {
        unsigned a = (t + off < 1024) ? h[t + off] : 0u;
        __syncthreads();
        h[t] += a;
        __syncthreads();
    }
    unsigned cum = h[t], nxt = (t + 1 < 1024) ? h[t + 1] : 0u;
    if (cum >= r2 && nxt < r2)
        g_Tbits = (g_B1 << 21) | (b2 << 10) | (unsigned)t;
}

// ---------------- K9: fused output ----------------
__device__ __forceinline__ float outval(float h, float p, float e, float s, unsigned T) {
    float enr = h + ((f2ord(s) >= T) ? 1.0f : 0.0f);
    // sign(log eps - log(1-eps) + log(p+1e-8) - log(1-p+1e-8)) == sign(e*pa - (1-e)*pb)
    float pa = __fadd_rn(p, 1e-8f);
    float pb = __fadd_rn(__fsub_rn(1.0f, p), 1e-8f);
    float eb = __fsub_rn(1.0f, e);
    double lhs = (double)e  * (double)pa;
    double rhs = (double)eb * (double)pb;
    return (lhs > rhs) ? enr : 0.0f;
}

__global__ void k_final(const float* __restrict__ H, const float* __restrict__ P,
                        const float* __restrict__ Eps, float* __restrict__ out) {
    unsigned T = g_Tbits;
    int i  = blockIdx.x * blockDim.x + threadIdx.x;
    int st = gridDim.x * blockDim.x;
    const float4* H4 = (const float4*)H;
    const float4* P4 = (const float4*)P;
    const float4* E4 = (const float4*)Eps;
    const float4* S4 = (const float4*)g_S;
    float4* O4 = (float4*)out;
    for (int j = i; j < NM / 4; j += st) {
        float4 h4 = H4[j], p4 = P4[j], e4 = E4[j], s4 = S4[j];
        float4 o;
        o.x = outval(h4.x, p4.x, e4.x, s4.x, T);
        o.y = outval(h4.y, p4.y, e4.y, s4.y, T);
        o.z = outval(h4.z, p4.z, e4.z, s4.z, T);
        o.w = outval(h4.w, p4.w, e4.w, s4.w, T);
        O4[j] = o;
    }
}

// ---------------- launch ----------------
extern "C" void kernel_launch(void* const* d_in, const int* in_sizes, int n_in,
                              void* d_out, int out_size) {
    const float* X   = (const float*)d_in[0];
    const float* H   = (const float*)d_in[1];
    const int*   V   = (const int*)d_in[2];
    const int*   E   = (const int*)d_in[3];
    const float* P   = (const float*)d_in[4];
    const float* W   = (const float*)d_in[5];
    const float* Eps = (const float*)d_in[6];
    float* out = (float*)d_out;

    k_zero<<<512, 256>>>();
    k_scatter<<<(NNZ * 32) / 256, 256>>>(X, V, E);
    {
        dim3 fg(NN, 2);
        k_feat<<<fg, 128>>>(X, W);
    }
    {
        dim3 gg(32, 32);
        k_gemm<<<gg, 256>>>();
    }
    k_mask<<<NNZ / 256, 256>>>(V, E);
    k_hist<<<2048, 256>>>();
    k_pick<<<1, 1024>>>();
    k_collect<<<2048, 256>>>();
    k_select<<<1, 1024>>>();
    k_final<<<4096, 256>>>(H, P, Eps, out);
}

// round 2
// speedup vs baseline: 1.1319x; 1.1319x over previous
#include <cuda_runtime.h>

#define NN   4096
#define MMm  4096
#define DD   128
#define CC   4
#define NNZ  262144
#define KDIM 512
#define KADD 26214
#define NM   (NN * MMm)
#define CAPC (4u * 1024u * 1024u)
#define PADA 4
#define LDA  (128 + PADA)

// ---------------- scratch (static device memory; no allocs allowed) ----------------
__device__ long long g_exsum[MMm * DD];      // fixed-point (2^32) segment sums
__device__ int       g_cnt[MMm];             // segment counts
__device__ float     g_nodef[NN * KDIM];     // 0.5 * normalized node features
__device__ float     g_edgef[MMm * KDIM];    // 0.5 * normalized edge features
__device__ float     g_S[NM];                // similarity matrix (masked)
__device__ unsigned  g_hist[2048];           // top-11-bit histogram
__device__ unsigned  g_cand[CAPC];           // candidate ordered-uints in threshold bucket
__device__ unsigned  g_candCount;
__device__ unsigned  g_B1;                   // selected top-11-bit bucket
__device__ unsigned  g_r1;                   // rank within bucket (1-based)
__device__ unsigned  g_Tbits;                // exact k-th largest value (ordered bits)

__device__ __forceinline__ unsigned f2ord(float f) {
    unsigned u = __float_as_uint(f);
    return (u & 0x80000000u) ? ~u : (u | 0x80000000u);
}

// ---------------- K0: zero transient state (runs every replay) ----------------
__global__ void k_zero() {
    int i  = blockIdx.x * blockDim.x + threadIdx.x;
    int st = gridDim.x * blockDim.x;
    for (int j = i; j < MMm * DD; j += st) g_exsum[j] = 0;
    for (int j = i; j < MMm;      j += st) g_cnt[j]   = 0;
    for (int j = i; j < 2048;     j += st) g_hist[j]  = 0;
    if (i == 0) g_candCount = 0;
}

// ---------------- K1: deterministic segment-sum via fixed-point atomics ----------------
__global__ void k_scatter(const float* __restrict__ X,
                          const int* __restrict__ V, const int* __restrict__ E) {
    int gid = blockIdx.x * blockDim.x + threadIdx.x;
    int i = gid >> 5;
    if (i >= NNZ) return;
    int q = gid & 31;
    int v = V[i], e = E[i];
    const float4 x = *reinterpret_cast<const float4*>(X + (size_t)v * DD + q * 4);
    unsigned long long* dst =
        reinterpret_cast<unsigned long long*>(g_exsum + (size_t)e * DD + q * 4);
    atomicAdd(dst + 0, (unsigned long long)__double2ll_rn((double)x.x * 4294967296.0));
    atomicAdd(dst + 1, (unsigned long long)__double2ll_rn((double)x.y * 4294967296.0));
    atomicAdd(dst + 2, (unsigned long long)__double2ll_rn((double)x.z * 4294967296.0));
    atomicAdd(dst + 3, (unsigned long long)__double2ll_rn((double)x.w * 4294967296.0));
    if (q == 0) atomicAdd(&g_cnt[e], 1);
}

// ---------------- K2: build 0.5 * l2norm(x * w_c) features ----------------
__global__ void k_feat(const float* __restrict__ X, const float* __restrict__ W) {
    int r   = blockIdx.x;
    int isE = blockIdx.y;
    int d   = threadIdx.x;   // 128 threads
    __shared__ float red[128];
    float x;
    if (!isE) {
        x = X[(size_t)r * DD + d];
    } else {
        long long s = g_exsum[(size_t)r * DD + d];
        float cnt   = (float)g_cnt[r];
        float sum   = (float)((double)s * (1.0 / 4294967296.0));
        x = __fdiv_rn(sum, fmaxf(cnt, 1.0f));
    }
    float* dst = isE ? g_edgef : g_nodef;
#pragma unroll
    for (int c = 0; c < CC; c++) {
        float v = x * W[c * DD + d];
        red[d] = v * v;
        __syncthreads();
        for (int s2 = 64; s2 > 0; s2 >>= 1) {
            if (d < s2) red[d] += red[d + s2];
            __syncthreads();
        }
        float nrm = __fsqrt_rn(red[0]);
        __syncthreads();
        dst[(size_t)r * KDIM + c * DD + d] = 0.5f * __fdiv_rn(v, fmaxf(nrm, 1e-12f));
    }
}

// ---------------- K3: FP32 SGEMM  S = A(4096x512) * B(4096x512)^T ----------------
// 128x128 tile, 256 threads, 8x8/thread with 4+4 split mapping:
//   rows: {ty*4+i, ty*4+64+i}, cols: {tx*4+j, tx*4+64+j}
// => B-frag LDS.128 are conflict-free (16B thread stride), A-frag are broadcasts.
// Smem rows padded (+4 floats) to kill staging STS conflicts.
__global__ void __launch_bounds__(256, 2) k_gemm() {
    const float* __restrict__ A = g_nodef;
    const float* __restrict__ B = g_edgef;
    float* __restrict__ S = g_S;

    __shared__ float As[2][8][LDA];
    __shared__ float Bs[2][8][LDA];
    const int tid = threadIdx.x;
    const int tx = tid & 15, ty = tid >> 4;
    const int bm = blockIdx.y * 128, bn = blockIdx.x * 128;
    const int lr = tid >> 1, lc = (tid & 1) * 4;
    const float* Ag = A + (size_t)(bm + lr) * KDIM + lc;
    const float* Bg = B + (size_t)(bn + lr) * KDIM + lc;

    float4 a4 = *(const float4*)Ag;
    float4 b4 = *(const float4*)Bg;

    float acc[8][8];
#pragma unroll
    for (int i = 0; i < 8; i++)
#pragma unroll
        for (int j = 0; j < 8; j++) acc[i][j] = 0.0f;

    As[0][lc + 0][lr] = a4.x; As[0][lc + 1][lr] = a4.y;
    As[0][lc + 2][lr] = a4.z; As[0][lc + 3][lr] = a4.w;
    Bs[0][lc + 0][lr] = b4.x; Bs[0][lc + 1][lr] = b4.y;
    Bs[0][lc + 2][lr] = b4.z; Bs[0][lc + 3][lr] = b4.w;
    __syncthreads();

    int buf = 0;
    const int NT = KDIM / 8;
    for (int kt = 0; kt < NT; kt++) {
        if (kt + 1 < NT) {
            a4 = *(const float4*)(Ag + (kt + 1) * 8);
            b4 = *(const float4*)(Bg + (kt + 1) * 8);
        }
#pragma unroll
        for (int kk = 0; kk < 8; kk++) {
            float ar[8], br[8];
            *(float4*)(ar)     = *(const float4*)&As[buf][kk][ty * 4];
            *(float4*)(ar + 4) = *(const float4*)&As[buf][kk][ty * 4 + 64];
            *(float4*)(br)     = *(const float4*)&Bs[buf][kk][tx * 4];
            *(float4*)(br + 4) = *(const float4*)&Bs[buf][kk][tx * 4 + 64];
#pragma unroll
            for (int i = 0; i < 8; i++)
#pragma unroll
                for (int j = 0; j < 8; j++) acc[i][j] += ar[i] * br[j];
        }
        if (kt + 1 < NT) {
            int nb = buf ^ 1;
            As[nb][lc + 0][lr] = a4.x; As[nb][lc + 1][lr] = a4.y;
            As[nb][lc + 2][lr] = a4.z; As[nb][lc + 3][lr] = a4.w;
            Bs[nb][lc + 0][lr] = b4.x; Bs[nb][lc + 1][lr] = b4.y;
            Bs[nb][lc + 2][lr] = b4.z; Bs[nb][lc + 3][lr] = b4.w;
            __syncthreads();
            buf = nb;
        }
    }
#pragma unroll
    for (int i = 0; i < 8; i++) {
        int row = bm + ty * 4 + (i & 3) + (i >> 2) * 64;
        float* dst = S + (size_t)row * MMm + bn + tx * 4;
        *(float4*)(dst)      = make_float4(acc[i][0], acc[i][1], acc[i][2], acc[i][3]);
        *(float4*)(dst + 64) = make_float4(acc[i][4], acc[i][5], acc[i][6], acc[i][7]);
    }
}

// ---------------- K4: mask existing incidences (dedup-safe) ----------------
__global__ void k_mask(const int* __restrict__ V, const int* __restrict__ E) {
    int i = blockIdx.x * blockDim.x + threadIdx.x;
    if (i < NNZ) {
        atomicExch(&g_S[(size_t)V[i] * MMm + E[i]], -1e30f);
    }
}

// ---------------- K5: top-11-bit histogram ----------------
__global__ void k_hist() {
    __shared__ unsigned h[2048];
    for (int j = threadIdx.x; j < 2048; j += blockDim.x) h[j] = 0;
    __syncthreads();
    int i  = blockIdx.x * blockDim.x + threadIdx.x;
    int st = gridDim.x * blockDim.x;
    const float4* S4 = (const float4*)g_S;
    for (int j = i; j < NM / 4; j += st) {
        float4 s = S4[j];
        atomicAdd(&h[f2ord(s.x) >> 21], 1u);
        atomicAdd(&h[f2ord(s.y) >> 21], 1u);
        atomicAdd(&h[f2ord(s.z) >> 21], 1u);
        atomicAdd(&h[f2ord(s.w) >> 21], 1u);
    }
    __syncthreads();
    for (int j = threadIdx.x; j < 2048; j += blockDim.x)
        if (h[j]) atomicAdd(&g_hist[j], h[j]);
}

// ---------------- K6: find threshold bucket (1 block, 1024 thr) ----------------
__global__ void k_pick() {
    __shared__ unsigned c[2048];
    int t = threadIdx.x;
    c[t] = g_hist[t];
    c[t + 1024] = g_hist[t + 1024];
    __syncthreads();
    for (int off = 1; off < 2048; off <<= 1) {
        unsigned a0 = (t + off < 2048) ? c[t + off] : 0u;
        unsigned a1 = (t + 1024 + off < 2048) ? c[t + 1024 + off] : 0u;
        __syncthreads();
        c[t] += a0; c[t + 1024] += a1;
        __syncthreads();
    }
    for (int b = t; b < 2048; b += 1024) {
        unsigned cum = c[b], nxt = (b + 1 < 2048) ? c[b + 1] : 0u;
        if (cum >= (unsigned)KADD && nxt < (unsigned)KADD) {
            g_B1 = (unsigned)b;
            g_r1 = (unsigned)KADD - nxt;
        }
    }
}

// ---------------- K7: collect candidates in threshold bucket ----------------
__global__ void k_collect() {
    unsigned B1 = g_B1;
    int i  = blockIdx.x * blockDim.x + threadIdx.x;
    int st = gridDim.x * blockDim.x;
    const float4* S4 = (const float4*)g_S;
    for (int j = i; j < NM / 4; j += st) {
        float4 s = S4[j];
        unsigned u0 = f2ord(s.x), u1 = f2ord(s.y), u2 = f2ord(s.z), u3 = f2ord(s.w);
        if ((u0 >> 21) == B1) { unsigned p = atomicAdd(&g_candCount, 1u); if (p < CAPC) g_cand[p] = u0; }
        if ((u1 >> 21) == B1) { unsigned p = atomicAdd(&g_candCount, 1u); if (p < CAPC) g_cand[p] = u1; }
        if ((u2 >> 21) == B1) { unsigned p = atomicAdd(&g_candCount, 1u); if (p < CAPC) g_cand[p] = u2; }
        if ((u3 >> 21) == B1) { unsigned p = atomicAdd(&g_candCount, 1u); if (p < CAPC) g_cand[p] = u3; }
    }
}

// ---------------- K8: exact k-th value via 11+10 bit refine (1 block) ----------------
__global__ void k_select() {
    __shared__ unsigned h[2048];
    __shared__ unsigned sb2, sr2;
    int t = threadIdx.x;  // 1024
    unsigned nc = g_candCount; if (nc > CAPC) nc = CAPC;
    unsigned r1 = g_r1;

    h[t] = 0; h[t + 1024] = 0;
    __syncthreads();
    for (unsigned i = t; i < nc; i += 1024)
        atomicAdd(&h[(g_cand[i] >> 10) & 2047u], 1u);
    __syncthreads();
    for (int off = 1; off < 2048; off <<= 1) {
        unsigned a0 = (t + off < 2048) ? h[t + off] : 0u;
        unsigned a1 = (t + 1024 + off < 2048) ? h[t + 1024 + off] : 0u;
        __syncthreads();
        h[t] += a0; h[t + 1024] += a1;
        __syncthreads();
    }
    for (int b = t; b < 2048; b += 1024) {
        unsigned cum = h[b], nxt = (b + 1 < 2048) ? h[b + 1] : 0u;
        if (cum >= r1 && nxt < r1) { sb2 = (unsigned)b; sr2 = r1 - nxt; }
    }
    __syncthreads();
    unsigned b2 = sb2, r2 = sr2;

    h[t] = 0;
    __syncthreads();
    for (unsigned i = t; i < nc; i += 1024) {
        unsigned u = g_cand[i];
        if (((u >> 10) & 2047u) == b2) atomicAdd(&h[u & 1023u], 1u);
    }
    __syncthreads();
    for (int off = 1; off < 1024; off <<= 1) {
        unsigned a = (t + off < 1024) ? h[t + off] : 0u;
        __syncthreads();
        h[t] += a;
        __syncthreads();
    }
    unsigned cum = h[t], nxt = (t + 1 < 1024) ? h[t + 1] : 0u;
    if (cum >= r2 && nxt < r2)
        g_Tbits = (g_B1 << 21) | (b2 << 10) | (unsigned)t;
}

// ---------------- K9: fused output ----------------
__device__ __forceinline__ float outval(float h, float p, float e, float s, unsigned T) {
    float enr = h + ((f2ord(s) >= T) ? 1.0f : 0.0f);
    // sign(log eps - log(1-eps) + log(p+1e-8) - log(1-p+1e-8)) == sign(e*pa - (1-e)*pb)
    float pa = __fadd_rn(p, 1e-8f);
    float pb = __fadd_rn(__fsub_rn(1.0f, p), 1e-8f);
    float eb = __fsub_rn(1.0f, e);
    double lhs = (double)e  * (double)pa;
    double rhs = (double)eb * (double)pb;
    return (lhs > rhs) ? enr : 0.0f;
}

__global__ void k_final(const float* __restrict__ H, const float* __restrict__ P,
                        const float* __restrict__ Eps, float* __restrict__ out) {
    unsigned T = g_Tbits;
    int i  = blockIdx.x * blockDim.x + threadIdx.x;
    int st = gridDim.x * blockDim.x;
    const float4* H4 = (const float4*)H;
    const float4* P4 = (const float4*)P;
    const float4* E4 = (const float4*)Eps;
    const float4* S4 = (const float4*)g_S;
    float4* O4 = (float4*)out;
    for (int j = i; j < NM / 4; j += st) {
        float4 h4 = H4[j], p4 = P4[j], e4 = E4[j], s4 = S4[j];
        float4 o;
        o.x = outval(h4.x, p4.x, e4.x, s4.x, T);
        o.y = outval(h4.y, p4.y, e4.y, s4.y, T);
        o.z = outval(h4.z, p4.z, e4.z, s4.z, T);
        o.w = outval(h4.w, p4.w, e4.w, s4.w, T);
        O4[j] = o;
    }
}

// ---------------- launch ----------------
extern "C" void kernel_launch(void* const* d_in, const int* in_sizes, int n_in,
                              void* d_out, int out_size) {
    const float* X   = (const float*)d_in[0];
    const float* H   = (const float*)d_in[1];
    const int*   V   = (const int*)d_in[2];
    const int*   E   = (const int*)d_in[3];
    const float* P   = (const float*)d_in[4];
    const float* W   = (const float*)d_in[5];
    const float* Eps = (const float*)d_in[6];
    float* out = (float*)d_out;

    k_zero<<<512, 256>>>();
    k_scatter<<<(NNZ * 32) / 256, 256>>>(X, V, E);
    {
        dim3 fg(NN, 2);
        k_feat<<<fg, 128>>>(X, W);
    }
    {
        dim3 gg(32, 32);
        k_gemm<<<gg, 256>>>();
    }
    k_mask<<<NNZ / 256, 256>>>(V, E);
    k_hist<<<2048, 256>>>();
    k_pick<<<1, 1024>>>();
    k_collect<<<2048, 256>>>();
    k_select<<<1, 1024>>>();
    k_final<<<4096, 256>>>(H, P, Eps, out);
}

// round 5
// speedup vs baseline: 1.2058x; 1.0652x over previous
#include <cuda_runtime.h>
#include <cstdint>

#define NN   4096
#define MMm  4096
#define DD   128
#define CC   4
#define NNZ  262144
#define KDIM 512
#define KADD 26214
#define NM   (NN * MMm)
#define CAPC (4u * 1024u * 1024u)

// GEMM tiling (mma.sync tf32 path)
#define MT      128
#define NT      128
#define KCH     32
#define NCHUNK  (KDIM / KCH)          // 16
#define LDK     36                    // padded k-stride in floats (32+4)
#define PLANE_F (128 * LDK)           // 4608 floats per plane
#define STAGE_F (4 * PLANE_F)         // 18432 floats per stage
#define SMEM_BYTES (2 * STAGE_F * 4)  // 147456 bytes

// ---------------- scratch (static device memory; no allocs allowed) ----------------
__device__ long long g_exsum[MMm * DD];      // fixed-point (2^32) segment sums
__device__ int       g_cnt[MMm];             // segment counts
__device__ float     g_Ahi[NN * KDIM];       // node feature tf32 hi plane
__device__ float     g_Alo[NN * KDIM];       // node feature tf32 lo plane
__device__ float     g_Bhi[MMm * KDIM];      // edge feature tf32 hi plane
__device__ float     g_Blo[MMm * KDIM];      // edge feature tf32 lo plane
__device__ float     g_S[NM];                // similarity matrix (masked)
__device__ unsigned  g_hist[2048];
__device__ unsigned  g_cand[CAPC];
__device__ unsigned  g_candCount;
__device__ unsigned  g_B1;
__device__ unsigned  g_r1;
__device__ unsigned  g_Tbits;

__device__ __forceinline__ unsigned f2ord(float f) {
    unsigned u = __float_as_uint(f);
    return (u & 0x80000000u) ? ~u : (u | 0x80000000u);
}
__device__ __forceinline__ float tf32r(float x) {
    uint32_t o;
    asm("cvt.rna.tf32.f32 %0, %1;" : "=r"(o) : "f"(x));
    return __uint_as_float(o);
}
__device__ __forceinline__ void cpa16(uint32_t dst, const void* src) {
    asm volatile("cp.async.cg.shared.global [%0], [%1], 16;"
                 :: "r"(dst), "l"(__cvta_generic_to_global(src)) : "memory");
}
// m16n8k8 tf32 mma: D = A*B + D  (row.col), fp32 accumulate
__device__ __forceinline__ void mma8(float* c,
                                     uint32_t a0, uint32_t a1, uint32_t a2, uint32_t a3,
                                     uint32_t b0, uint32_t b1) {
    asm volatile(
        "mma.sync.aligned.m16n8k8.row.col.f32.tf32.tf32.f32 "
        "{%0,%1,%2,%3}, {%4,%5,%6,%7}, {%8,%9}, {%0,%1,%2,%3};"
        : "+f"(c[0]), "+f"(c[1]), "+f"(c[2]), "+f"(c[3])
        : "r"(a0), "r"(a1), "r"(a2), "r"(a3), "r"(b0), "r"(b1));
}

// ---------------- K0: zero transient state (runs every replay) ----------------
__global__ void k_zero() {
    int i  = blockIdx.x * blockDim.x + threadIdx.x;
    int st = gridDim.x * blockDim.x;
    for (int j = i; j < MMm * DD; j += st) g_exsum[j] = 0;
    for (int j = i; j < MMm;      j += st) g_cnt[j]   = 0;
    for (int j = i; j < 2048;     j += st) g_hist[j]  = 0;
    if (i == 0) g_candCount = 0;
}

// ---------------- K1: deterministic segment-sum via fixed-point atomics ----------------
__global__ void k_scatter(const float* __restrict__ X,
                          const int* __restrict__ V, const int* __restrict__ E) {
    int gid = blockIdx.x * blockDim.x + threadIdx.x;
    int i = gid >> 5;
    if (i >= NNZ) return;
    int q = gid & 31;
    int v = V[i], e = E[i];
    const float4 x = *reinterpret_cast<const float4*>(X + (size_t)v * DD + q * 4);
    unsigned long long* dst =
        reinterpret_cast<unsigned long long*>(g_exsum + (size_t)e * DD + q * 4);
    atomicAdd(dst + 0, (unsigned long long)__double2ll_rn((double)x.x * 4294967296.0));
    atomicAdd(dst + 1, (unsigned long long)__double2ll_rn((double)x.y * 4294967296.0));
    atomicAdd(dst + 2, (unsigned long long)__double2ll_rn((double)x.z * 4294967296.0));
    atomicAdd(dst + 3, (unsigned long long)__double2ll_rn((double)x.w * 4294967296.0));
    if (q == 0) atomicAdd(&g_cnt[e], 1);
}

// ---------------- K2: build 0.5 * l2norm(x * w_c) features, tf32 hi/lo planes ----------------
__global__ void k_feat(const float* __restrict__ X, const float* __restrict__ W) {
    int r   = blockIdx.x;
    int isE = blockIdx.y;
    int d   = threadIdx.x;   // 128 threads
    __shared__ float red[128];
    float x;
    if (!isE) {
        x = X[(size_t)r * DD + d];
    } else {
        long long s = g_exsum[(size_t)r * DD + d];
        float cnt   = (float)g_cnt[r];
        float sum   = (float)((double)s * (1.0 / 4294967296.0));
        x = __fdiv_rn(sum, fmaxf(cnt, 1.0f));
    }
    float* dhi = isE ? g_Bhi : g_Ahi;
    float* dlo = isE ? g_Blo : g_Alo;
#pragma unroll
    for (int c = 0; c < CC; c++) {
        float v = x * W[c * DD + d];
        red[d] = v * v;
        __syncthreads();
        for (int s2 = 64; s2 > 0; s2 >>= 1) {
            if (d < s2) red[d] += red[d + s2];
            __syncthreads();
        }
        float nrm = __fsqrt_rn(red[0]);
        __syncthreads();
        float val = 0.5f * __fdiv_rn(v, fmaxf(nrm, 1e-12f));
        float hi = tf32r(val);
        float lo = tf32r(val - hi);
        dhi[(size_t)r * KDIM + c * DD + d] = hi;
        dlo[(size_t)r * KDIM + c * DD + d] = lo;
    }
}

// ---------------- K3: 3xTF32 mma.sync GEMM  S = A(4096x512) * B(4096x512)^T ----------------
// 128x128 CTA tile, 8 warps (2x4), warp tile 64x32, k-chunk 32, double-buffered cp.async.
__global__ void __launch_bounds__(256, 1) k_gemm() {
    extern __shared__ __align__(128) float smf[];
    uint32_t sb;
    asm("{ .reg .u64 t; cvta.to.shared.u64 t, %1; cvt.u32.u64 %0, t; }"
        : "=r"(sb) : "l"(smf));
    const int tid = threadIdx.x;
    const int wid = tid >> 5, lane = tid & 31;
    const int g = lane >> 2, t = lane & 3;
    const int wm = wid >> 2, wn = wid & 3;
    const int bm = blockIdx.y * MT, bn = blockIdx.x * NT;

    float acc[4][4][4];
#pragma unroll
    for (int mt = 0; mt < 4; mt++)
#pragma unroll
        for (int nt = 0; nt < 4; nt++)
#pragma unroll
            for (int r = 0; r < 4; r++) acc[mt][nt][r] = 0.0f;

    // ---- chunk loader: 4 planes x 1024 float4 via cp.async ----
    auto load_chunk = [&](int kt, int stage) {
        uint32_t base = sb + (uint32_t)stage * (STAGE_F * 4);
        const float* gp0 = g_Ahi; const float* gp1 = g_Alo;
        const float* gp2 = g_Bhi; const float* gp3 = g_Blo;
#pragma unroll
        for (int i = 0; i < 4; i++) {
            int idx = tid + i * 256;
            int row = idx >> 3, c4 = idx & 7;
            uint32_t so = (uint32_t)(row * (LDK * 4) + c4 * 16);
            size_t goA = (size_t)(bm + row) * KDIM + kt * KCH + c4 * 4;
            size_t goB = (size_t)(bn + row) * KDIM + kt * KCH + c4 * 4;
            cpa16(base + so,                     gp0 + goA);
            cpa16(base + PLANE_F * 4     + so,   gp1 + goA);
            cpa16(base + PLANE_F * 8     + so,   gp2 + goB);
            cpa16(base + PLANE_F * 12    + so,   gp3 + goB);
        }
        asm volatile("cp.async.commit_group;" ::: "memory");
    };

    load_chunk(0, 0);

    for (int kt = 0; kt < NCHUNK; kt++) {
        int buf = kt & 1;
        if (kt + 1 < NCHUNK) {
            load_chunk(kt + 1, buf ^ 1);
            asm volatile("cp.async.wait_group 1;" ::: "memory");
        } else {
            asm volatile("cp.async.wait_group 0;" ::: "memory");
        }
        __syncthreads();

        const float* st_ = smf + buf * STAGE_F;
        const float* Ah = st_;
        const float* Al = st_ + PLANE_F;
        const float* Bh = st_ + 2 * PLANE_F;
        const float* Bl = st_ + 3 * PLANE_F;

#pragma unroll
        for (int ks = 0; ks < 4; ks++) {
            const int kb = ks * 8;
            uint32_t bh[4][2], bl[4][2];
#pragma unroll
            for (int nt = 0; nt < 4; nt++) {
                int n0 = wn * 32 + nt * 8 + g;
                int o  = n0 * LDK + kb + t;
                bh[nt][0] = __float_as_uint(Bh[o]);
                bh[nt][1] = __float_as_uint(Bh[o + 4]);
                bl[nt][0] = __float_as_uint(Bl[o]);
                bl[nt][1] = __float_as_uint(Bl[o + 4]);
            }
#pragma unroll
            for (int mt = 0; mt < 4; mt++) {
                int r0 = wm * 64 + mt * 16 + g;
                int o0 = r0 * LDK + kb + t;
                int o1 = (r0 + 8) * LDK + kb + t;
                uint32_t ah0 = __float_as_uint(Ah[o0]);
                uint32_t ah1 = __float_as_uint(Ah[o1]);
                uint32_t ah2 = __float_as_uint(Ah[o0 + 4]);
                uint32_t ah3 = __float_as_uint(Ah[o1 + 4]);
                uint32_t al0 = __float_as_uint(Al[o0]);
                uint32_t al1 = __float_as_uint(Al[o1]);
                uint32_t al2 = __float_as_uint(Al[o0 + 4]);
                uint32_t al3 = __float_as_uint(Al[o1 + 4]);
#pragma unroll
                for (int nt = 0; nt < 4; nt++) {
                    mma8(acc[mt][nt], ah0, ah1, ah2, ah3, bh[nt][0], bh[nt][1]);
                    mma8(acc[mt][nt], ah0, ah1, ah2, ah3, bl[nt][0], bl[nt][1]);
                    mma8(acc[mt][nt], al0, al1, al2, al3, bh[nt][0], bh[nt][1]);
                }
            }
        }
        __syncthreads();
    }

    // ---- epilogue: c0:(g,2t) c1:(g,2t+1) c2:(g+8,2t) c3:(g+8,2t+1) ----
#pragma unroll
    for (int mt = 0; mt < 4; mt++) {
        int r0 = bm + wm * 64 + mt * 16 + g;
#pragma unroll
        for (int nt = 0; nt < 4; nt++) {
            int c = bn + wn * 32 + nt * 8 + 2 * t;
            *(float2*)(g_S + (size_t)r0 * MMm + c)       = make_float2(acc[mt][nt][0], acc[mt][nt][1]);
            *(float2*)(g_S + (size_t)(r0 + 8) * MMm + c) = make_float2(acc[mt][nt][2], acc[mt][nt][3]);
        }
    }
}

// ---------------- K4: mask existing incidences (dedup-safe) ----------------
__global__ void k_mask(const int* __restrict__ V, const int* __restrict__ E) {
    int i = blockIdx.x * blockDim.x + threadIdx.x;
    if (i < NNZ) {
        atomicExch(&g_S[(size_t)V[i] * MMm + E[i]], -1e30f);
    }
}

// ---------------- K5: top-11-bit histogram ----------------
__global__ void k_hist() {
    __shared__ unsigned h[2048];
    for (int j = threadIdx.x; j < 2048; j += blockDim.x) h[j] = 0;
    __syncthreads();
    int i  = blockIdx.x * blockDim.x + threadIdx.x;
    int st = gridDim.x * blockDim.x;
    const float4* S4 = (const float4*)g_S;
    for (int j = i; j < NM / 4; j += st) {
        float4 s = S4[j];
        atomicAdd(&h[f2ord(s.x) >> 21], 1u);
        atomicAdd(&h[f2ord(s.y) >> 21], 1u);
        atomicAdd(&h[f2ord(s.z) >> 21], 1u);
        atomicAdd(&h[f2ord(s.w) >> 21], 1u);
    }
    __syncthreads();
    for (int j = threadIdx.x; j < 2048; j += blockDim.x)
        if (h[j]) atomicAdd(&g_hist[j], h[j]);
}

// ---------------- K6: find threshold bucket (1 block, 1024 thr) ----------------
__global__ void k_pick() {
    __shared__ unsigned c[2048];
    int t = threadIdx.x;
    c[t] = g_hist[t];
    c[t + 1024] = g_hist[t + 1024];
    __syncthreads();
    for (int off = 1; off < 2048; off <<= 1) {
        unsigned a0 = (t + off < 2048) ? c[t + off] : 0u;
        unsigned a1 = (t + 1024 + off < 2048) ? c[t + 1024 + off] : 0u;
        __syncthreads();
        c[t] += a0; c[t + 1024] += a1;
        __syncthreads();
    }
    for (int b = t; b < 2048; b += 1024) {
        unsigned cum = c[b], nxt = (b + 1 < 2048) ? c[b + 1] : 0u;
        if (cum >= (unsigned)KADD && nxt < (unsigned)KADD) {
            g_B1 = (unsigned)b;
            g_r1 = (unsigned)KADD - nxt;
        }
    }
}

// ---------------- K7: collect candidates in threshold bucket ----------------
__global__ void k_collect() {
    unsigned B1 = g_B1;
    int i  = blockIdx.x * blockDim.x + threadIdx.x;
    int st = gridDim.x * blockDim.x;
    const float4* S4 = (const float4*)g_S;
    for (int j = i; j < NM / 4; j += st) {
        float4 s = S4[j];
        unsigned u0 = f2ord(s.x), u1 = f2ord(s.y), u2 = f2ord(s.z), u3 = f2ord(s.w);
        if ((u0 >> 21) == B1) { unsigned p = atomicAdd(&g_candCount, 1u); if (p < CAPC) g_cand[p] = u0; }
        if ((u1 >> 21) == B1) { unsigned p = atomicAdd(&g_candCount, 1u); if (p < CAPC) g_cand[p] = u1; }
        if ((u2 >> 21) == B1) { unsigned p = atomicAdd(&g_candCount, 1u); if (p < CAPC) g_cand[p] = u2; }
        if ((u3 >> 21) == B1) { unsigned p = atomicAdd(&g_candCount, 1u); if (p < CAPC) g_cand[p] = u3; }
    }
}

// ---------------- K8: exact k-th value via 11+10 bit refine (1 block) ----------------
__global__ void k_select() {
    __shared__ unsigned h[2048];
    __shared__ unsigned sb2, sr2;
    int t = threadIdx.x;  // 1024
    unsigned nc = g_candCount; if (nc > CAPC) nc = CAPC;
    unsigned r1 = g_r1;

    h[t] = 0; h[t + 1024] = 0;
    __syncthreads();
    for (unsigned i = t; i < nc; i += 1024)
        atomicAdd(&h[(g_cand[i] >> 10) & 2047u], 1u);
    __syncthreads();
    for (int off = 1; off < 2048; off <<= 1) {
        unsigned a0 = (t + off < 2048) ? h[t + off] : 0u;
        unsigned a1 = (t + 1024 + off < 2048) ? h[t + 1024 + off] : 0u;
        __syncthreads();
        h[t] += a0; h[t + 1024] += a1;
        __syncthreads();
    }
    for (int b = t; b < 2048; b += 1024) {
        unsigned cum = h[b], nxt = (b + 1 < 2048) ? h[b + 1] : 0u;
        if (cum >= r1 && nxt < r1) { sb2 = (unsigned)b; sr2 = r1 - nxt; }
    }
    __syncthreads();
    unsigned b2 = sb2, r2 = sr2;

    h[t] = 0;
    __syncthreads();
    for (unsigned i = t; i < nc; i += 1024) {
        unsigned u = g_cand[i];
        if (((u >> 10) & 2047u) == b2) atomicAdd(&h[u & 1023u], 1u);
    }
    __syncthreads();
    for (int off = 1; off < 1024; off <<= 1) {
        unsigned a = (t + off < 1024) ? h[t + off] : 0u;
        __syncthreads();
        h[t] += a;
        __syncthreads();
    }
    unsigned cum = h[t], nxt = (t + 1 < 1024) ? h[t + 1] : 0u;
    if (cum >= r2 && nxt < r2)
        g_Tbits = (g_B1 << 21) | (b2 << 10) | (unsigned)t;
}

// ---------------- K9: fused output ----------------
__device__ __forceinline__ float outval(float h, float p, float e, float s, unsigned T) {
    float enr = h + ((f2ord(s) >= T) ? 1.0f : 0.0f);
    float pa = __fadd_rn(p, 1e-8f);
    float pb = __fadd_rn(__fsub_rn(1.0f, p), 1e-8f);
    float eb = __fsub_rn(1.0f, e);
    double lhs = (double)e  * (double)pa;
    double rhs = (double)eb * (double)pb;
    return (lhs > rhs) ? enr : 0.0f;
}

__global__ void k_final(const float* __restrict__ H, const float* __restrict__ P,
                        const float* __restrict__ Eps, float* __restrict__ out) {
    unsigned T = g_Tbits;
    int i  = blockIdx.x * blockDim.x + threadIdx.x;
    int st = gridDim.x * blockDim.x;
    const float4* H4 = (const float4*)H;
    const float4* P4 = (const float4*)P;
    const float4* E4 = (const float4*)Eps;
    const float4* S4 = (const float4*)g_S;
    float4* O4 = (float4*)out;
    for (int j = i; j < NM / 4; j += st) {
        float4 h4 = H4[j], p4 = P4[j], e4 = E4[j], s4 = S4[j];
        float4 o;
        o.x = outval(h4.x, p4.x, e4.x, s4.x, T);
        o.y = outval(h4.y, p4.y, e4.y, s4.y, T);
        o.z = outval(h4.z, p4.z, e4.z, s4.z, T);
        o.w = outval(h4.w, p4.w, e4.w, s4.w, T);
        O4[j] = o;
    }
}

// ---------------- launch ----------------
extern "C" void kernel_launch(void* const* d_in, const int* in_sizes, int n_in,
                              void* d_out, int out_size) {
    const float* X   = (const float*)d_in[0];
    const float* H   = (const float*)d_in[1];
    const int*   V   = (const int*)d_in[2];
    const int*   E   = (const int*)d_in[3];
    const float* P   = (const float*)d_in[4];
    const float* W   = (const float*)d_in[5];
    const float* Eps = (const float*)d_in[6];
    float* out = (float*)d_out;

    cudaFuncSetAttribute(k_gemm, cudaFuncAttributeMaxDynamicSharedMemorySize, SMEM_BYTES);

    k_zero<<<512, 256>>>();
    k_scatter<<<(NNZ * 32) / 256, 256>>>(X, V, E);
    {
        dim3 fg(NN, 2);
        k_feat<<<fg, 128>>>(X, W);
    }
    {
        dim3 gg(MMm / NT, NN / MT);   // (32, 32)
        k_gemm<<<gg, 256, SMEM_BYTES>>>();
    }
    k_mask<<<NNZ / 256, 256>>>(V, E);
    k_hist<<<2048, 256>>>();
    k_pick<<<1, 1024>>>();
    k_collect<<<2048, 256>>>();
    k_select<<<1, 1024>>>();
    k_final<<<4096, 256>>>(H, P, Eps, out);
}

// round 6
// speedup vs baseline: 1.4346x; 1.1898x over previous
#include <cuda_runtime.h>
#include <cstdint>

#define NN   4096
#define MMm  4096
#define DD   128
#define CC   4
#define NNZ  262144
#define KDIM 512
#define KADD 26214
#define NM   (NN * MMm)
#define CAPC (4u * 1024u * 1024u)

// GEMM tiling (mma.sync tf32 path)
#define MT      128
#define NT      128
#define KCH     32
#define NCHUNK  (KDIM / KCH)          // 16
#define LDK     36                    // padded k-stride in floats (32+4)
#define PLANE_F (128 * LDK)           // 4608 floats per plane
#define STAGE_F (4 * PLANE_F)         // 18432 floats per stage
#define SMEM_BYTES (2 * STAGE_F * 4)  // 147456 bytes
#define GT      512                   // gemm threads

// ---------------- scratch (static device memory; no allocs allowed) ----------------
__device__ long long g_exsum[MMm * DD];      // fixed-point (2^32) segment sums
__device__ int       g_cnt[MMm];             // segment counts
__device__ unsigned  g_eoff[MMm + 1];        // CSR offsets
__device__ unsigned  g_ecur[MMm];            // fill cursors
__device__ int       g_eidx[NNZ];            // CSR node indices
__device__ float     g_Ahi[NN * KDIM];       // node feature tf32 hi plane
__device__ float     g_Alo[NN * KDIM];       // node feature tf32 lo plane
__device__ float     g_Bhi[MMm * KDIM];      // edge feature tf32 hi plane
__device__ float     g_Blo[MMm * KDIM];      // edge feature tf32 lo plane
__device__ float     g_S[NM];                // similarity matrix (masked)
__device__ unsigned  g_hist[2048];
__device__ unsigned  g_cand[CAPC];
__device__ unsigned  g_candCount;
__device__ unsigned  g_B1;
__device__ unsigned  g_r1;
__device__ unsigned  g_Tbits;

__device__ __forceinline__ unsigned f2ord(float f) {
    unsigned u = __float_as_uint(f);
    return (u & 0x80000000u) ? ~u : (u | 0x80000000u);
}
__device__ __forceinline__ float tf32r(float x) {
    uint32_t o;
    asm("cvt.rna.tf32.f32 %0, %1;" : "=r"(o) : "f"(x));
    return __uint_as_float(o);
}
__device__ __forceinline__ void cpa16(uint32_t dst, const void* src) {
    asm volatile("cp.async.cg.shared.global [%0], [%1], 16;"
                 :: "r"(dst), "l"(__cvta_generic_to_global(src)) : "memory");
}
// m16n8k8 tf32 mma: D = A*B + D  (row.col), fp32 accumulate
__device__ __forceinline__ void mma8(float* c,
                                     uint32_t a0, uint32_t a1, uint32_t a2, uint32_t a3,
                                     uint32_t b0, uint32_t b1) {
    asm volatile(
        "mma.sync.aligned.m16n8k8.row.col.f32.tf32.tf32.f32 "
        "{%0,%1,%2,%3}, {%4,%5,%6,%7}, {%8,%9}, {%0,%1,%2,%3};"
        : "+f"(c[0]), "+f"(c[1]), "+f"(c[2]), "+f"(c[3])
        : "r"(a0), "r"(a1), "r"(a2), "r"(a3), "r"(b0), "r"(b1));
}

// ---------------- K0: zero transient state (runs every replay) ----------------
__global__ void k_zero() {
    int i  = blockIdx.x * blockDim.x + threadIdx.x;
    int st = gridDim.x * blockDim.x;
    for (int j = i; j < MMm;  j += st) { g_cnt[j] = 0; g_ecur[j] = 0; }
    for (int j = i; j < 2048; j += st) g_hist[j] = 0;
    if (i == 0) g_candCount = 0;
}

// ---------------- CSR build: count -> prefix -> fill ----------------
__global__ void k_count(const int* __restrict__ E) {
    int i = blockIdx.x * blockDim.x + threadIdx.x;
    if (i < NNZ) atomicAdd(&g_cnt[E[i]], 1);
}

__global__ void k_prefix() {   // exclusive prefix of g_cnt into g_eoff (1 block, 1024 thr)
    __shared__ unsigned s[1024];
    int t = threadIdx.x;
    unsigned c0 = g_cnt[4*t], c1 = g_cnt[4*t+1], c2 = g_cnt[4*t+2], c3 = g_cnt[4*t+3];
    s[t] = c0 + c1 + c2 + c3;
    __syncthreads();
    for (int off = 1; off < 1024; off <<= 1) {
        unsigned v = (t >= off) ? s[t - off] : 0u;
        __syncthreads();
        s[t] += v;
        __syncthreads();
    }
    unsigned base = t ? s[t-1] : 0u;
    g_eoff[4*t]   = base;
    g_eoff[4*t+1] = base + c0;
    g_eoff[4*t+2] = base + c0 + c1;
    g_eoff[4*t+3] = base + c0 + c1 + c2;
    if (t == 1023) g_eoff[MMm] = s[1023];
}

__global__ void k_fill(const int* __restrict__ V, const int* __restrict__ E) {
    int i = blockIdx.x * blockDim.x + threadIdx.x;
    if (i < NNZ) {
        int e = E[i];
        unsigned pos = atomicAdd(&g_ecur[e], 1u);
        g_eidx[g_eoff[e] + pos] = V[i];
    }
}

// ---------------- K1: per-edge gather-sum (fixed-point, register-resident, deterministic) ----------------
__global__ void k_emean(const float* __restrict__ X) {
    int e = blockIdx.x;
    int d = threadIdx.x;   // 128 threads = dims
    unsigned s0 = g_eoff[e], s1 = g_eoff[e + 1];
    long long acc = 0;
    for (unsigned j = s0; j < s1; j++) {
        int v = g_eidx[j];
        float x = X[(size_t)v * DD + d];
        acc += __double2ll_rn((double)x * 4294967296.0);
    }
    g_exsum[(size_t)e * DD + d] = acc;
}

// ---------------- K2: build 0.5 * l2norm(x * w_c) features, tf32 hi/lo planes ----------------
__global__ void k_feat(const float* __restrict__ X, const float* __restrict__ W) {
    int r   = blockIdx.x;
    int isE = blockIdx.y;
    int d   = threadIdx.x;   // 128 threads
    __shared__ float red[128];
    float x;
    if (!isE) {
        x = X[(size_t)r * DD + d];
    } else {
        long long s = g_exsum[(size_t)r * DD + d];
        float cnt   = (float)g_cnt[r];
        float sum   = (float)((double)s * (1.0 / 4294967296.0));
        x = __fdiv_rn(sum, fmaxf(cnt, 1.0f));
    }
    float* dhi = isE ? g_Bhi : g_Ahi;
    float* dlo = isE ? g_Blo : g_Alo;
#pragma unroll
    for (int c = 0; c < CC; c++) {
        float v = x * W[c * DD + d];
        red[d] = v * v;
        __syncthreads();
        for (int s2 = 64; s2 > 0; s2 >>= 1) {
            if (d < s2) red[d] += red[d + s2];
            __syncthreads();
        }
        float nrm = __fsqrt_rn(red[0]);
        __syncthreads();
        float val = 0.5f * __fdiv_rn(v, fmaxf(nrm, 1e-12f));
        float hi = tf32r(val);
        float lo = tf32r(val - hi);
        dhi[(size_t)r * KDIM + c * DD + d] = hi;
        dlo[(size_t)r * KDIM + c * DD + d] = lo;
    }
}

// ---------------- K3: 3xTF32 mma.sync GEMM  S = A(4096x512) * B(4096x512)^T ----------------
// 128x128 CTA tile, 16 warps (4x4), warp tile 32x32, k-chunk 32, double-buffered cp.async.
__global__ void __launch_bounds__(GT, 1) k_gemm() {
    extern __shared__ __align__(128) float smf[];
    uint32_t sb;
    asm("{ .reg .u64 t; cvta.to.shared.u64 t, %1; cvt.u32.u64 %0, t; }"
        : "=r"(sb) : "l"(smf));
    const int tid = threadIdx.x;
    const int wid = tid >> 5, lane = tid & 31;
    const int g = lane >> 2, t = lane & 3;
    const int wm = wid >> 2, wn = wid & 3;
    const int bm = blockIdx.y * MT, bn = blockIdx.x * NT;

    float acc[2][4][4];
#pragma unroll
    for (int mt = 0; mt < 2; mt++)
#pragma unroll
        for (int nt = 0; nt < 4; nt++)
#pragma unroll
            for (int r = 0; r < 4; r++) acc[mt][nt][r] = 0.0f;

    // ---- chunk loader: 4 planes x 1024 float4 via cp.async (8 per thread) ----
    auto load_chunk = [&](int kt, int stage) {
        uint32_t base = sb + (uint32_t)stage * (STAGE_F * 4);
#pragma unroll
        for (int i = 0; i < 2; i++) {
            int idx = tid + i * GT;
            int row = idx >> 3, c4 = idx & 7;
            uint32_t so = (uint32_t)(row * (LDK * 4) + c4 * 16);
            size_t goA = (size_t)(bm + row) * KDIM + kt * KCH + c4 * 4;
            size_t goB = (size_t)(bn + row) * KDIM + kt * KCH + c4 * 4;
            cpa16(base + so,                  g_Ahi + goA);
            cpa16(base + PLANE_F * 4  + so,   g_Alo + goA);
            cpa16(base + PLANE_F * 8  + so,   g_Bhi + goB);
            cpa16(base + PLANE_F * 12 + so,   g_Blo + goB);
        }
        asm volatile("cp.async.commit_group;" ::: "memory");
    };

    load_chunk(0, 0);

    for (int kt = 0; kt < NCHUNK; kt++) {
        int buf = kt & 1;
        if (kt + 1 < NCHUNK) {
            load_chunk(kt + 1, buf ^ 1);
            asm volatile("cp.async.wait_group 1;" ::: "memory");
        } else {
            asm volatile("cp.async.wait_group 0;" ::: "memory");
        }
        __syncthreads();

        const float* st_ = smf + buf * STAGE_F;
        const float* Ah = st_;
        const float* Al = st_ + PLANE_F;
        const float* Bh = st_ + 2 * PLANE_F;
        const float* Bl = st_ + 3 * PLANE_F;

#pragma unroll
        for (int ks = 0; ks < 4; ks++) {
            const int kb = ks * 8;
            uint32_t bh[4][2], bl[4][2];
#pragma unroll
            for (int nt = 0; nt < 4; nt++) {
                int n0 = wn * 32 + nt * 8 + g;
                int o  = n0 * LDK + kb + t;
                bh[nt][0] = __float_as_uint(Bh[o]);
                bh[nt][1] = __float_as_uint(Bh[o + 4]);
                bl[nt][0] = __float_as_uint(Bl[o]);
                bl[nt][1] = __float_as_uint(Bl[o + 4]);
            }
#pragma unroll
            for (int mt = 0; mt < 2; mt++) {
                int r0 = wm * 32 + mt * 16 + g;
                int o0 = r0 * LDK + kb + t;
                int o1 = (r0 + 8) * LDK + kb + t;
                uint32_t ah0 = __float_as_uint(Ah[o0]);
                uint32_t ah1 = __float_as_uint(Ah[o1]);
                uint32_t ah2 = __float_as_uint(Ah[o0 + 4]);
                uint32_t ah3 = __float_as_uint(Ah[o1 + 4]);
                uint32_t al0 = __float_as_uint(Al[o0]);
                uint32_t al1 = __float_as_uint(Al[o1]);
                uint32_t al2 = __float_as_uint(Al[o0 + 4]);
                uint32_t al3 = __float_as_uint(Al[o1 + 4]);
#pragma unroll
                for (int nt = 0; nt < 4; nt++) {
                    mma8(acc[mt][nt], ah0, ah1, ah2, ah3, bh[nt][0], bh[nt][1]);
                    mma8(acc[mt][nt], ah0, ah1, ah2, ah3, bl[nt][0], bl[nt][1]);
                    mma8(acc[mt][nt], al0, al1, al2, al3, bh[nt][0], bh[nt][1]);
                }
            }
        }
        __syncthreads();
    }

    // ---- epilogue: c0:(g,2t) c1:(g,2t+1) c2:(g+8,2t) c3:(g+8,2t+1) ----
#pragma unroll
    for (int mt = 0; mt < 2; mt++) {
        int r0 = bm + wm * 32 + mt * 16 + g;
#pragma unroll
        for (int nt = 0; nt < 4; nt++) {
            int c = bn + wn * 32 + nt * 8 + 2 * t;
            *(float2*)(g_S + (size_t)r0 * MMm + c)       = make_float2(acc[mt][nt][0], acc[mt][nt][1]);
            *(float2*)(g_S + (size_t)(r0 + 8) * MMm + c) = make_float2(acc[mt][nt][2], acc[mt][nt][3]);
        }
    }
}

// ---------------- K4: mask existing incidences (dedup-safe) ----------------
__global__ void k_mask(const int* __restrict__ V, const int* __restrict__ E) {
    int i = blockIdx.x * blockDim.x + threadIdx.x;
    if (i < NNZ) {
        atomicExch(&g_S[(size_t)V[i] * MMm + E[i]], -1e30f);
    }
}

// ---------------- K5: top-11-bit histogram ----------------
__global__ void k_hist() {
    __shared__ unsigned h[2048];
    for (int j = threadIdx.x; j < 2048; j += blockDim.x) h[j] = 0;
    __syncthreads();
    int i  = blockIdx.x * blockDim.x + threadIdx.x;
    int st = gridDim.x * blockDim.x;
    const float4* S4 = (const float4*)g_S;
    for (int j = i; j < NM / 4; j += st) {
        float4 s = S4[j];
        atomicAdd(&h[f2ord(s.x) >> 21], 1u);
        atomicAdd(&h[f2ord(s.y) >> 21], 1u);
        atomicAdd(&h[f2ord(s.z) >> 21], 1u);
        atomicAdd(&h[f2ord(s.w) >> 21], 1u);
    }
    __syncthreads();
    for (int j = threadIdx.x; j < 2048; j += blockDim.x)
        if (h[j]) atomicAdd(&g_hist[j], h[j]);
}

// ---------------- K6: find threshold bucket (1 block, 1024 thr) ----------------
__global__ void k_pick() {
    __shared__ unsigned c[2048];
    int t = threadIdx.x;
    c[t] = g_hist[t];
    c[t + 1024] = g_hist[t + 1024];
    __syncthreads();
    for (int off = 1; off < 2048; off <<= 1) {
        unsigned a0 = (t + off < 2048) ? c[t + off] : 0u;
        unsigned a1 = (t + 1024 + off < 2048) ? c[t + 1024 + off] : 0u;
        __syncthreads();
        c[t] += a0; c[t + 1024] += a1;
        __syncthreads();
    }
    for (int b = t; b < 2048; b += 1024) {
        unsigned cum = c[b], nxt = (b + 1 < 2048) ? c[b + 1] : 0u;
        if (cum >= (unsigned)KADD && nxt < (unsigned)KADD) {
            g_B1 = (unsigned)b;
            g_r1 = (unsigned)KADD - nxt;
        }
    }
}

// ---------------- K7: collect candidates in threshold bucket ----------------
__global__ void k_collect() {
    unsigned B1 = g_B1;
    int i  = blockIdx.x * blockDim.x + threadIdx.x;
    int st = gridDim.x * blockDim.x;
    const float4* S4 = (const float4*)g_S;
    for (int j = i; j < NM / 4; j += st) {
        float4 s = S4[j];
        unsigned u0 = f2ord(s.x), u1 = f2ord(s.y), u2 = f2ord(s.z), u3 = f2ord(s.w);
        if ((u0 >> 21) == B1) { unsigned p = atomicAdd(&g_candCount, 1u); if (p < CAPC) g_cand[p] = u0; }
        if ((u1 >> 21) == B1) { unsigned p = atomicAdd(&g_candCount, 1u); if (p < CAPC) g_cand[p] = u1; }
        if ((u2 >> 21) == B1) { unsigned p = atomicAdd(&g_candCount, 1u); if (p < CAPC) g_cand[p] = u2; }
        if ((u3 >> 21) == B1) { unsigned p = atomicAdd(&g_candCount, 1u); if (p < CAPC) g_cand[p] = u3; }
    }
}

// ---------------- K8: exact k-th value via 11+10 bit refine (1 block) ----------------
__global__ void k_select() {
    __shared__ unsigned h[2048];
    __shared__ unsigned sb2, sr2;
    int t = threadIdx.x;  // 1024
    unsigned nc = g_candCount; if (nc > CAPC) nc = CAPC;
    unsigned r1 = g_r1;

    h[t] = 0; h[t + 1024] = 0;
    __syncthreads();
    for (unsigned i = t; i < nc; i += 1024)
        atomicAdd(&h[(g_cand[i] >> 10) & 2047u], 1u);
    __syncthreads();
    for (int off = 1; off < 2048; off <<= 1) {
        unsigned a0 = (t + off < 2048) ? h[t + off] : 0u;
        unsigned a1 = (t + 1024 + off < 2048) ? h[t + 1024 + off] : 0u;
        __syncthreads();
        h[t] += a0; h[t + 1024] += a1;
        __syncthreads();
    }
    for (int b = t; b < 2048; b += 1024) {
        unsigned cum = h[b], nxt = (b + 1 < 2048) ? h[b + 1] : 0u;
        if (cum >= r1 && nxt < r1) { sb2 = (unsigned)b; sr2 = r1 - nxt; }
    }
    __syncthreads();
    unsigned b2 = sb2, r2 = sr2;

    h[t] = 0;
    __syncthreads();
    for (unsigned i = t; i < nc; i += 1024) {
        unsigned u = g_cand[i];
        if (((u >> 10) & 2047u) == b2) atomicAdd(&h[u & 1023u], 1u);
    }
    __syncthreads();
    for (int off = 1; off < 1024; off <<= 1) {
        unsigned a = (t + off < 1024) ? h[t + off] : 0u;
        __syncthreads();
        h[t] += a;
        __syncthreads();
    }
    unsigned cum = h[t], nxt = (t + 1 < 1024) ? h[t + 1] : 0u;
    if (cum >= r2 && nxt < r2)
        g_Tbits = (g_B1 << 21) | (b2 << 10) | (unsigned)t;
}

// ---------------- K9: fused output ----------------
__device__ __forceinline__ float outval(float h, float p, float e, float s, unsigned T) {
    float enr = h + ((f2ord(s) >= T) ? 1.0f : 0.0f);
    float pa = __fadd_rn(p, 1e-8f);
    float pb = __fadd_rn(__fsub_rn(1.0f, p), 1e-8f);
    float eb = __fsub_rn(1.0f, e);
    double lhs = (double)e  * (double)pa;
    double rhs = (double)eb * (double)pb;
    return (lhs > rhs) ? enr : 0.0f;
}

__global__ void k_final(const float* __restrict__ H, const float* __restrict__ P,
                        const float* __restrict__ Eps, float* __restrict__ out) {
    unsigned T = g_Tbits;
    int i  = blockIdx.x * blockDim.x + threadIdx.x;
    int st = gridDim.x * blockDim.x;
    const float4* H4 = (const float4*)H;
    const float4* P4 = (const float4*)P;
    const float4* E4 = (const float4*)Eps;
    const float4* S4 = (const float4*)g_S;
    float4* O4 = (float4*)out;
    for (int j = i; j < NM / 4; j += st) {
        float4 h4 = H4[j], p4 = P4[j], e4 = E4[j], s4 = S4[j];
        float4 o;
        o.x = outval(h4.x, p4.x, e4.x, s4.x, T);
        o.y = outval(h4.y, p4.y, e4.y, s4.y, T);
        o.z = outval(h4.z, p4.z, e4.z, s4.z, T);
        o.w = outval(h4.w, p4.w, e4.w, s4.w, T);
        O4[j] = o;
    }
}

// ---------------- launch ----------------
extern "C" void kernel_launch(void* const* d_in, const int* in_sizes, int n_in,
                              void* d_out, int out_size) {
    const float* X   = (const float*)d_in[0];
    const float* H   = (const float*)d_in[1];
    const int*   V   = (const int*)d_in[2];
    const int*   E   = (const int*)d_in[3];
    const float* P   = (const float*)d_in[4];
    const float* W   = (const float*)d_in[5];
    const float* Eps = (const float*)d_in[6];
    float* out = (float*)d_out;

    cudaFuncSetAttribute(k_gemm, cudaFuncAttributeMaxDynamicSharedMemorySize, SMEM_BYTES);

    k_zero<<<64, 256>>>();
    k_count<<<NNZ / 256, 256>>>(E);
    k_prefix<<<1, 1024>>>();
    k_fill<<<NNZ / 256, 256>>>(V, E);
    k_emean<<<MMm, 128>>>(X);
    {
        dim3 fg(NN, 2);
        k_feat<<<fg, 128>>>(X, W);
    }
    {
        dim3 gg(MMm / NT, NN / MT);   // (32, 32)
        k_gemm<<<gg, GT, SMEM_BYTES>>>();
    }
    k_mask<<<NNZ / 256, 256>>>(V, E);
    k_hist<<<2048, 256>>>();
    k_pick<<<1, 1024>>>();
    k_collect<<<2048, 256>>>();
    k_select<<<1, 1024>>>();
    k_final<<<4096, 256>>>(H, P, Eps, out);
}